// round 15
// baseline (speedup 1.0000x reference)
#include <cuda_runtime.h>
#include <cuda_fp16.h>
#include <math.h>
#include <stdint.h>

// ---------------- problem constants ----------------
#define BATCH   32
#define NPATCH  196
#define TOK     (BATCH * NPATCH)   // 6272
#define DMODEL  768
#define NHEAD   12
#define HDIM    64
#define NLAYER  12
#define HIDDEN  3072
#define QKVN    (3 * DMODEL)       // 2304
#define IMG     224
#define PSZ     16
#define GRID_   14

// ---------------- scratch (no allocations allowed) ----------------
__device__ float  g_h  [(size_t)TOK * DMODEL];     // residual stream (fp32)
__device__ __half h_qkv[(size_t)TOK * QKVN];       // qkv (half)
__device__ __half h_xp [(size_t)TOK * DMODEL];     // patchified input (half)
__device__ __half h_y  [(size_t)TOK * DMODEL];     // LN output (half)
__device__ __half h_o  [(size_t)TOK * DMODEL];     // attention output (half)
__device__ __half h_act[(size_t)TOK * HIDDEN];     // GELU output (half)
// half weights, native [K,N] layout (B operand via ldmatrix.trans)
__device__ __half w_pe  [(size_t)DMODEL * DMODEL];   // conv_w transposed -> [K,N]
__device__ __half w_qkv [(size_t)NLAYER * DMODEL * QKVN];
__device__ __half w_proj[(size_t)NLAYER * DMODEL * DMODEL];
__device__ __half w_f1  [(size_t)NLAYER * DMODEL * HIDDEN];
__device__ __half w_f2  [(size_t)NLAYER * HIDDEN * DMODEL];

// ---------------- helpers ----------------
__device__ __forceinline__ uint32_t smem_u32(const void* p) {
    uint32_t a;
    asm("{ .reg .u64 t; cvta.to.shared.u64 t, %1; cvt.u32.u64 %0, t; }" : "=r"(a) : "l"(p));
    return a;
}
__device__ __forceinline__ void cpasync16(void* dst, const void* src) {
    uint32_t d = (uint32_t)__cvta_generic_to_shared(dst);
    asm volatile("cp.async.cg.shared.global [%0], [%1], 16;" :: "r"(d), "l"(src));
}
__device__ __forceinline__ void ldmx4(uint32_t* r, uint32_t addr) {
    asm volatile("ldmatrix.sync.aligned.m8n8.x4.shared.b16 {%0,%1,%2,%3}, [%4];"
                 : "=r"(r[0]), "=r"(r[1]), "=r"(r[2]), "=r"(r[3]) : "r"(addr));
}
__device__ __forceinline__ void ldmx4t(uint32_t* r, uint32_t addr) {
    asm volatile("ldmatrix.sync.aligned.m8n8.x4.trans.shared.b16 {%0,%1,%2,%3}, [%4];"
                 : "=r"(r[0]), "=r"(r[1]), "=r"(r[2]), "=r"(r[3]) : "r"(addr));
}
__device__ __forceinline__ void mma_f16(float* c, const uint32_t* a,
                                        uint32_t b0, uint32_t b1) {
    asm volatile(
        "mma.sync.aligned.m16n8k16.row.col.f32.f16.f16.f32 "
        "{%0,%1,%2,%3}, {%4,%5,%6,%7}, {%8,%9}, {%0,%1,%2,%3};"
        : "+f"(c[0]), "+f"(c[1]), "+f"(c[2]), "+f"(c[3])
        : "r"(a[0]), "r"(a[1]), "r"(a[2]), "r"(a[3]), "r"(b0), "r"(b1));
}
__device__ __forceinline__ uint32_t h2u(float x, float y) {
    __half2 h = __floats2half2_rn(x, y);
    return *(uint32_t*)&h;
}

// ---------------- weight conversion ----------------
__global__ void cvt_half4_kernel(const float* __restrict__ src, __half* __restrict__ dst,
                                 int n4) {
    int i = blockIdx.x * blockDim.x + threadIdx.x;
    if (i >= n4) return;
    float4 v = ((const float4*)src)[i];
    __half2 a = __floats2half2_rn(v.x, v.y);
    __half2 b = __floats2half2_rn(v.z, v.w);
    uint2 u = make_uint2(*(uint32_t*)&a, *(uint32_t*)&b);
    ((uint2*)dst)[i] = u;
}
__global__ void tr_half_kernel(const float* __restrict__ src, __half* __restrict__ dst,
                               int K, int N) {
    __shared__ float t[32][33];
    size_t off = (size_t)blockIdx.z * K * N;
    src += off; dst += off;
    int kb = blockIdx.y * 32, nb = blockIdx.x * 32;
    for (int i = threadIdx.y; i < 32; i += 8)
        t[i][threadIdx.x] = src[(size_t)(kb + i) * N + nb + threadIdx.x];
    __syncthreads();
    for (int i = threadIdx.y; i < 32; i += 8)
        dst[(size_t)(nb + i) * K + kb + threadIdx.x] = __float2half_rn(t[threadIdx.x][i]);
}

// ---------------- patchify -> half ----------------
__global__ void patch_kernel(const float* __restrict__ x, __half* __restrict__ xp) {
    int idx = blockIdx.x * blockDim.x + threadIdx.x;
    if (idx >= TOK * DMODEL) return;
    int t = idx / DMODEL;
    int f = idx - t * DMODEL;
    int b = t / NPATCH;
    int p = t - b * NPATCH;
    int gy = p / GRID_, gx = p - gy * GRID_;
    int c  = f >> 8;
    int py = (f >> 4) & 15;
    int px = f & 15;
    xp[idx] = __float2half_rn(
        x[(((size_t)b * 3 + c) * IMG + gy * PSZ + py) * IMG + gx * PSZ + px]);
}

// ---------------- FP16 mma.sync GEMM (B in [K,N] via ldmatrix.trans) ----------------
// CTA 128x128, 8 warps (2x4 grid of 64x32 tiles), 256 threads, 2 CTAs/SM,
// k-chunk 64, 3-stage ring, prefetch distance 2.
// OP 0: +bias -> HALF ; 1: +bias+res -> fp32 ; 2: +bias,GELU -> HALF ; 3: +bias+pos -> fp32
#define KCH  64
#define ASTR 72
#define BSTR 136                                  // 128 + 8 pad halfs
#define A_HALFS (128 * ASTR)                      // 9216
#define B_HALFS (KCH * BSTR)                      // 8704
#define STAGE_HALFS (A_HALFS + B_HALFS)           // 17920
#define STAGE_BYTES (STAGE_HALFS * 2)             // 35840
#define GSTAGES 3
#define GEMM_SMEM (GSTAGES * STAGE_BYTES)         // 107520

template <int OP>
__global__ void __launch_bounds__(256, 2)
gemm_fp16(const __half* __restrict__ A, const __half* __restrict__ B,
          const float* __restrict__ bias, const float* __restrict__ res,
          void* __restrict__ Cout, int M, int N, int K) {
    extern __shared__ __half sm[];
    const int tid = threadIdx.x;                  // 256 threads
    const int m0 = blockIdx.y * 128, n0 = blockIdx.x * 128;
    const int warp = tid >> 5, lane = tid & 31;
    const int wm = warp >> 2, wn = warp & 3;      // 2x4 warp grid, 64x32 tiles
    const int g = lane >> 2, tg = lane & 3;

    const uint32_t smb = smem_u32(sm);
    uint32_t aAddr[4], bAddr[2];
#pragma unroll
    for (int mi = 0; mi < 4; mi++)
        aAddr[mi] = smb + ((wm * 64 + mi * 16 + (lane & 15)) * ASTR +
                           ((lane >> 4) & 1) * 8) * 2;
    // trans B: row = k (lane&7 + ((lane>>3)&1)*8), col = wn*32 + n2*16 + ((lane>>4)&1)*8
#pragma unroll
    for (int n2 = 0; n2 < 2; n2++)
        bAddr[n2] = smb + A_HALFS * 2 +
                    (((lane & 7) + ((lane >> 3) & 1) * 8) * BSTR +
                     wn * 32 + n2 * 16 + ((lane >> 4) & 1) * 8) * 2;

    float acc[4][4][4];
#pragma unroll
    for (int i = 0; i < 4; i++)
#pragma unroll
        for (int j = 0; j < 4; j++)
#pragma unroll
            for (int c = 0; c < 4; c++) acc[i][j][c] = 0.f;

    const int nIter = K >> 6;

    auto load_stage = [&](int it) {
        __half* As = sm + (it % GSTAGES) * STAGE_HALFS;
        __half* Bs = As + A_HALFS;
        int k0 = it * KCH;
        const __half* Ag = A + (size_t)m0 * K + k0;
        const __half* Bg = B + (size_t)k0 * N + n0;
#pragma unroll
        for (int i = 0; i < 4; i++) {             // A: 128 rows x 8 chunks of 8 halfs
            int idx = tid + i * 256;
            int r = idx >> 3, c = (idx & 7) * 8;
            cpasync16(&As[r * ASTR + c], Ag + (size_t)r * K + c);
        }
#pragma unroll
        for (int i = 0; i < 4; i++) {             // B: 64 k-rows x 16 chunks of 8 halfs
            int idx = tid + i * 256;
            int r = idx >> 4, c = (idx & 15) * 8;
            cpasync16(&Bs[r * BSTR + c], Bg + (size_t)r * N + c);
        }
        asm volatile("cp.async.commit_group;");
    };

    load_stage(0);
    load_stage(1);

    for (int it = 0; it < nIter; it++) {
        if (it + 2 < nIter) load_stage(it + 2);
        int rem = nIter - 1 - it;
        if (rem >= 2)      asm volatile("cp.async.wait_group 2;");
        else if (rem == 1) asm volatile("cp.async.wait_group 1;");
        else               asm volatile("cp.async.wait_group 0;");
        __syncthreads();

        uint32_t stOff = (uint32_t)((it % GSTAGES) * STAGE_BYTES);
#pragma unroll
        for (int kk = 0; kk < 4; kk++) {
            uint32_t a[4][4], b[2][4];
#pragma unroll
            for (int mi = 0; mi < 4; mi++) ldmx4(a[mi], aAddr[mi] + stOff + kk * 32);
#pragma unroll
            for (int n2 = 0; n2 < 2; n2++)
                ldmx4t(b[n2], bAddr[n2] + stOff + kk * 16 * BSTR * 2);
#pragma unroll
            for (int mi = 0; mi < 4; mi++)
#pragma unroll
                for (int n2 = 0; n2 < 2; n2++) {
                    mma_f16(acc[mi][n2 * 2 + 0], a[mi], b[n2][0], b[n2][1]);
                    mma_f16(acc[mi][n2 * 2 + 1], a[mi], b[n2][2], b[n2][3]);
                }
        }
        __syncthreads();
    }

    // ---- epilogue ----
    float* Cf = (float*)Cout;
    __half* Ch = (__half*)Cout;
#pragma unroll
    for (int mi = 0; mi < 4; mi++) {
        int r0 = m0 + wm * 64 + mi * 16 + g;
#pragma unroll
        for (int ni = 0; ni < 4; ni++) {
            int n = n0 + wn * 32 + ni * 8 + tg * 2;
            float2 bi = *(const float2*)(bias + n);
#pragma unroll
            for (int half = 0; half < 2; half++) {
                int m = r0 + half * 8;
                float v0 = acc[mi][ni][half * 2 + 0] + bi.x;
                float v1 = acc[mi][ni][half * 2 + 1] + bi.y;
                if (OP == 1) {
                    float2 rv = *(const float2*)(res + (size_t)m * N + n);
                    v0 += rv.x; v1 += rv.y;
                }
                if (OP == 3) {
                    float2 rv = *(const float2*)(res + (size_t)(m % NPATCH) * N + n);
                    v0 += rv.x; v1 += rv.y;
                }
                if (OP == 2) {
                    v0 = 0.5f * v0 * (1.0f + erff(v0 * 0.70710678118654752f));
                    v1 = 0.5f * v1 * (1.0f + erff(v1 * 0.70710678118654752f));
                }
                if (OP == 0 || OP == 2) {
                    *(__half2*)(Ch + (size_t)m * N + n) = __floats2half2_rn(v0, v1);
                } else {
                    *(float2*)(Cf + (size_t)m * N + n) = make_float2(v0, v1);
                }
            }
        }
    }
}

// ---------------- attention: tensor-core flash-lite, one CTA per (b,h) ----------------
#define QSTR 72
#define VSTR 216
#define QS_OFF 0
#define KS_OFF (208 * QSTR)
#define VT_OFF (2 * 208 * QSTR)
#define SMEM_ATTN ((VT_OFF + 64 * VSTR) * 2)   // 87552 bytes

__global__ void __launch_bounds__(256, 1)
attn_kernel(const __half* __restrict__ qkv, __half* __restrict__ o) {
    extern __shared__ __half smh[];
    const int tid = threadIdx.x;
    const int bh = blockIdx.x;
    const int b = bh / NHEAD, hh = bh - b * NHEAD;
    const __half* base = qkv + (size_t)b * NPATCH * QKVN + hh * HDIM;

    for (int i = tid; i < 64 * VSTR / 8; i += 256)
        ((uint4*)(smh + VT_OFF))[i] = make_uint4(0u, 0u, 0u, 0u);
    __syncthreads();
    for (int i = tid; i < 208 * 8; i += 256) {
        int r = i >> 3, c = (i & 7) * 8;
        int row = r < NPATCH ? r : NPATCH - 1;
        const __half* src = base + (size_t)row * QKVN;
        *(uint4*)(smh + QS_OFF + r * QSTR + c) = *(const uint4*)(src + c);
        *(uint4*)(smh + KS_OFF + r * QSTR + c) = *(const uint4*)(src + DMODEL + c);
    }
    for (int i = tid; i < NPATCH * 8; i += 256) {
        int kidx = i >> 3, c8 = (i & 7) * 8;
        uint4 v = *(const uint4*)(base + (size_t)kidx * QKVN + 2 * DMODEL + c8);
        const __half* vh = (const __half*)&v;
#pragma unroll
        for (int d = 0; d < 8; d++)
            smh[VT_OFF + (c8 + d) * VSTR + kidx] = vh[d];
    }
    __syncthreads();

    const int warp = tid >> 5, lane = tid & 31;
    const int g = lane >> 2, tg = lane & 3;
    const uint32_t smb = smem_u32(smh);
    const uint32_t qsB = smb + QS_OFF * 2;
    const uint32_t ksB = smb + KS_OFF * 2;
    const uint32_t vtB = smb + VT_OFF * 2;

    const uint32_t aRow = ((lane & 15) * QSTR + ((lane >> 4) & 1) * 8) * 2;
    const uint32_t bRowK = (((lane & 7) + ((lane >> 4) & 1) * 8) * QSTR + ((lane >> 3) & 1) * 8) * 2;
    const uint32_t bRowV = (((lane & 7) + ((lane >> 4) & 1) * 8) * VSTR + ((lane >> 3) & 1) * 8) * 2;

    for (int qc = warp; qc < 13; qc += 8) {
        int q0 = qc * 16;
        uint32_t qa[4][4];
#pragma unroll
        for (int kk = 0; kk < 4; kk++)
            ldmx4(qa[kk], qsB + q0 * QSTR * 2 + aRow + kk * 32);

        float sacc[26][4];
#pragma unroll
        for (int j = 0; j < 26; j++)
#pragma unroll
            for (int c = 0; c < 4; c++) sacc[j][c] = 0.f;

#pragma unroll
        for (int n2 = 0; n2 < 13; n2++) {
#pragma unroll
            for (int kk = 0; kk < 4; kk++) {
                uint32_t bk[4];
                ldmx4(bk, ksB + n2 * 16 * QSTR * 2 + bRowK + kk * 32);
                mma_f16(sacc[n2 * 2 + 0], qa[kk], bk[0], bk[1]);
                mma_f16(sacc[n2 * 2 + 1], qa[kk], bk[2], bk[3]);
            }
        }

        float m0 = -1e30f, m1 = -1e30f;
#pragma unroll
        for (int j = 0; j < 25; j++) {
            bool v = (j < 24) || (tg < 2);
            if (v) {
                m0 = fmaxf(m0, fmaxf(sacc[j][0], sacc[j][1]));
                m1 = fmaxf(m1, fmaxf(sacc[j][2], sacc[j][3]));
            }
        }
        m0 = fmaxf(m0, __shfl_xor_sync(0xffffffffu, m0, 1));
        m0 = fmaxf(m0, __shfl_xor_sync(0xffffffffu, m0, 2));
        m1 = fmaxf(m1, __shfl_xor_sync(0xffffffffu, m1, 1));
        m1 = fmaxf(m1, __shfl_xor_sync(0xffffffffu, m1, 2));

        float l0 = 0.f, l1 = 0.f;
#pragma unroll
        for (int j = 0; j < 26; j++) {
            bool v = (j < 24) || (j == 24 && tg < 2);
            float e0 = v ? __expf(0.125f * (sacc[j][0] - m0)) : 0.f;
            float e1 = v ? __expf(0.125f * (sacc[j][1] - m0)) : 0.f;
            float e2 = v ? __expf(0.125f * (sacc[j][2] - m1)) : 0.f;
            float e3 = v ? __expf(0.125f * (sacc[j][3] - m1)) : 0.f;
            sacc[j][0] = e0; sacc[j][1] = e1; sacc[j][2] = e2; sacc[j][3] = e3;
            l0 += e0 + e1; l1 += e2 + e3;
        }
        l0 += __shfl_xor_sync(0xffffffffu, l0, 1);
        l0 += __shfl_xor_sync(0xffffffffu, l0, 2);
        l1 += __shfl_xor_sync(0xffffffffu, l1, 1);
        l1 += __shfl_xor_sync(0xffffffffu, l1, 2);
        float i0 = 1.f / l0, i1 = 1.f / l1;

        uint32_t pa[13][4];
#pragma unroll
        for (int nt = 0; nt < 13; nt++) {
            pa[nt][0] = h2u(sacc[2 * nt][0] * i0, sacc[2 * nt][1] * i0);
            pa[nt][1] = h2u(sacc[2 * nt][2] * i1, sacc[2 * nt][3] * i1);
            pa[nt][2] = h2u(sacc[2 * nt + 1][0] * i0, sacc[2 * nt + 1][1] * i0);
            pa[nt][3] = h2u(sacc[2 * nt + 1][2] * i1, sacc[2 * nt + 1][3] * i1);
        }

        float oacc[8][4];
#pragma unroll
        for (int j = 0; j < 8; j++)
#pragma unroll
            for (int c = 0; c < 4; c++) oacc[j][c] = 0.f;

#pragma unroll
        for (int dn2 = 0; dn2 < 4; dn2++) {
#pragma unroll
            for (int nt = 0; nt < 13; nt++) {
                uint32_t bv[4];
                ldmx4(bv, vtB + dn2 * 16 * VSTR * 2 + bRowV + nt * 32);
                mma_f16(oacc[dn2 * 2 + 0], pa[nt], bv[0], bv[1]);
                mma_f16(oacc[dn2 * 2 + 1], pa[nt], bv[2], bv[3]);
            }
        }

        int r0 = q0 + g, r1 = q0 + g + 8;
        __half* ob = o + (size_t)b * NPATCH * DMODEL + hh * HDIM;
#pragma unroll
        for (int j8 = 0; j8 < 8; j8++) {
            int col = j8 * 8 + 2 * tg;
            if (r0 < NPATCH)
                *(__half2*)(ob + (size_t)r0 * DMODEL + col) =
                    __floats2half2_rn(oacc[j8][0], oacc[j8][1]);
            if (r1 < NPATCH)
                *(__half2*)(ob + (size_t)r1 * DMODEL + col) =
                    __floats2half2_rn(oacc[j8][2], oacc[j8][3]);
        }
    }
}

// ---------------- layernorm: float4 vectorized, 192 threads/row ----------------
template <int HALF_OUT>
__global__ void ln_kernel(const float* __restrict__ x, const float* __restrict__ w,
                          const float* __restrict__ bb, void* __restrict__ y) {
    int t = blockIdx.x;
    int tid = threadIdx.x;                    // 192
    float4 v = ((const float4*)(x + (size_t)t * DMODEL))[tid];
    float s  = v.x + v.y + v.z + v.w;
    float ss = v.x * v.x + v.y * v.y + v.z * v.z + v.w * v.w;
    __shared__ float redS[6], redQ[6];
#pragma unroll
    for (int off = 16; off; off >>= 1) {
        s  += __shfl_xor_sync(0xffffffffu, s,  off);
        ss += __shfl_xor_sync(0xffffffffu, ss, off);
    }
    if ((tid & 31) == 0) { redS[tid >> 5] = s; redQ[tid >> 5] = ss; }
    __syncthreads();
    if (tid == 0) {
        float a = 0.f, b2 = 0.f;
#pragma unroll
        for (int i = 0; i < 6; i++) { a += redS[i]; b2 += redQ[i]; }
        float mean = a * (1.0f / DMODEL);
        float var = b2 * (1.0f / DMODEL) - mean * mean;
        redS[0] = mean;
        redQ[0] = rsqrtf(var + 1e-5f);
    }
    __syncthreads();
    float mean = redS[0], rstd = redQ[0];
    float4 wv = ((const float4*)w)[tid];
    float4 bv = ((const float4*)bb)[tid];
    float o0 = (v.x - mean) * rstd * wv.x + bv.x;
    float o1 = (v.y - mean) * rstd * wv.y + bv.y;
    float o2 = (v.z - mean) * rstd * wv.z + bv.z;
    float o3 = (v.w - mean) * rstd * wv.w + bv.w;
    if (HALF_OUT) {
        __half2 a = __floats2half2_rn(o0, o1);
        __half2 b = __floats2half2_rn(o2, o3);
        ((uint2*)((__half*)y + (size_t)t * DMODEL))[tid] =
            make_uint2(*(uint32_t*)&a, *(uint32_t*)&b);
    } else {
        ((float4*)((float*)y + (size_t)t * DMODEL))[tid] = make_float4(o0, o1, o2, o3);
    }
}

// ---------------- launch ----------------
extern "C" void kernel_launch(void* const* d_in, const int* in_sizes, int n_in,
                              void* d_out, int out_size) {
    const float* x      = (const float*)d_in[0];
    const float* conv_w = (const float*)d_in[1];
    const float* conv_b = (const float*)d_in[2];
    const float* pos    = (const float*)d_in[3];
    const float* ln1w   = (const float*)d_in[4];
    const float* ln1b   = (const float*)d_in[5];
    const float* qkvw   = (const float*)d_in[6];
    const float* qkvb   = (const float*)d_in[7];
    const float* projw  = (const float*)d_in[8];
    const float* projb  = (const float*)d_in[9];
    const float* ln2w   = (const float*)d_in[10];
    const float* ln2b   = (const float*)d_in[11];
    const float* f1w    = (const float*)d_in[12];
    const float* f1b    = (const float*)d_in[13];
    const float* f2w    = (const float*)d_in[14];
    const float* f2b    = (const float*)d_in[15];
    const float* lnfw   = (const float*)d_in[16];
    const float* lnfb   = (const float*)d_in[17];
    float* out = (float*)d_out;

    float* h;
    __half *qkv, *xp, *y, *o, *act, *wpe, *rqkvw, *rprojw, *rf1w, *rf2w;
    cudaGetSymbolAddress((void**)&h,   g_h);
    cudaGetSymbolAddress((void**)&qkv, h_qkv);
    cudaGetSymbolAddress((void**)&xp,  h_xp);
    cudaGetSymbolAddress((void**)&y,   h_y);
    cudaGetSymbolAddress((void**)&o,   h_o);
    cudaGetSymbolAddress((void**)&act, h_act);
    cudaGetSymbolAddress((void**)&wpe, w_pe);
    cudaGetSymbolAddress((void**)&rqkvw,  w_qkv);
    cudaGetSymbolAddress((void**)&rprojw, w_proj);
    cudaGetSymbolAddress((void**)&rf1w,   w_f1);
    cudaGetSymbolAddress((void**)&rf2w,   w_f2);

    cudaFuncSetAttribute(attn_kernel, cudaFuncAttributeMaxDynamicSharedMemorySize, SMEM_ATTN);
    cudaFuncSetAttribute(gemm_fp16<0>, cudaFuncAttributeMaxDynamicSharedMemorySize, GEMM_SMEM);
    cudaFuncSetAttribute(gemm_fp16<1>, cudaFuncAttributeMaxDynamicSharedMemorySize, GEMM_SMEM);
    cudaFuncSetAttribute(gemm_fp16<2>, cudaFuncAttributeMaxDynamicSharedMemorySize, GEMM_SMEM);
    cudaFuncSetAttribute(gemm_fp16<3>, cudaFuncAttributeMaxDynamicSharedMemorySize, GEMM_SMEM);

    // weights -> half, native [K,N] layout (no transpose); conv_w [N,K] -> [K,N]
    {
        int n4;
        n4 = NLAYER * DMODEL * QKVN   / 4; cvt_half4_kernel<<<(n4 + 255) / 256, 256>>>(qkvw,  rqkvw,  n4);
        n4 = NLAYER * DMODEL * DMODEL / 4; cvt_half4_kernel<<<(n4 + 255) / 256, 256>>>(projw, rprojw, n4);
        n4 = NLAYER * DMODEL * HIDDEN / 4; cvt_half4_kernel<<<(n4 + 255) / 256, 256>>>(f1w,   rf1w,   n4);
        n4 = NLAYER * HIDDEN * DMODEL / 4; cvt_half4_kernel<<<(n4 + 255) / 256, 256>>>(f2w,   rf2w,   n4);
        tr_half_kernel<<<dim3(24, 24, 1), dim3(32, 8)>>>(conv_w, wpe, DMODEL, DMODEL);
    }

    // patchify + patch-embed GEMM (+bias +pos_embed)
    patch_kernel<<<(TOK * DMODEL + 255) / 256, 256>>>(x, xp);
    gemm_fp16<3><<<dim3(DMODEL / 128, TOK / 128), 256, GEMM_SMEM>>>(
        xp, wpe, conv_b, pos, h, TOK, DMODEL, DMODEL);

    for (int l = 0; l < NLAYER; l++) {
        ln_kernel<1><<<TOK, 192>>>(h, ln1w + (size_t)l * DMODEL, ln1b + (size_t)l * DMODEL, y);
        gemm_fp16<0><<<dim3(QKVN / 128, TOK / 128), 256, GEMM_SMEM>>>(
            y, rqkvw + (size_t)l * DMODEL * QKVN, qkvb + (size_t)l * QKVN, nullptr, qkv,
            TOK, QKVN, DMODEL);
        attn_kernel<<<BATCH * NHEAD, 256, SMEM_ATTN>>>(qkv, o);
        gemm_fp16<1><<<dim3(DMODEL / 128, TOK / 128), 256, GEMM_SMEM>>>(
            o, rprojw + (size_t)l * DMODEL * DMODEL, projb + (size_t)l * DMODEL, h, h,
            TOK, DMODEL, DMODEL);
        ln_kernel<1><<<TOK, 192>>>(h, ln2w + (size_t)l * DMODEL, ln2b + (size_t)l * DMODEL, y);
        gemm_fp16<2><<<dim3(HIDDEN / 128, TOK / 128), 256, GEMM_SMEM>>>(
            y, rf1w + (size_t)l * DMODEL * HIDDEN, f1b + (size_t)l * HIDDEN, nullptr, act,
            TOK, HIDDEN, DMODEL);
        gemm_fp16<1><<<dim3(DMODEL / 128, TOK / 128), 256, GEMM_SMEM>>>(
            act, rf2w + (size_t)l * HIDDEN * DMODEL, f2b + (size_t)l * DMODEL, h, h,
            TOK, DMODEL, HIDDEN);
    }
    ln_kernel<0><<<TOK, 192>>>(h, lnfw, lnfb, out);
}

// round 16
// speedup vs baseline: 1.0721x; 1.0721x over previous
#include <cuda_runtime.h>
#include <cuda_fp16.h>
#include <math.h>
#include <stdint.h>

// ---------------- problem constants ----------------
#define BATCH   32
#define NPATCH  196
#define TOK     (BATCH * NPATCH)   // 6272
#define DMODEL  768
#define NHEAD   12
#define HDIM    64
#define NLAYER  12
#define HIDDEN  3072
#define QKVN    (3 * DMODEL)       // 2304
#define IMG     224
#define PSZ     16
#define GRID_   14

// ---------------- scratch (no allocations allowed) ----------------
__device__ float  g_h  [(size_t)TOK * DMODEL];     // residual stream (fp32)
__device__ __half h_qkv[(size_t)TOK * QKVN];       // qkv (half)
__device__ __half h_xp [(size_t)TOK * DMODEL];     // patchified input (half)
__device__ __half h_y  [(size_t)TOK * DMODEL];     // LN output (half)
__device__ __half h_o  [(size_t)TOK * DMODEL];     // attention output (half)
__device__ __half h_act[(size_t)TOK * HIDDEN];     // GELU output (half)
// half weights, native [K,N] layout (B operand via ldmatrix.trans)
__device__ __half w_pe  [(size_t)DMODEL * DMODEL];   // conv_w transposed -> [K,N]
__device__ __half w_qkv [(size_t)NLAYER * DMODEL * QKVN];
__device__ __half w_proj[(size_t)NLAYER * DMODEL * DMODEL];
__device__ __half w_f1  [(size_t)NLAYER * DMODEL * HIDDEN];
__device__ __half w_f2  [(size_t)NLAYER * HIDDEN * DMODEL];

// ---------------- helpers ----------------
__device__ __forceinline__ uint32_t smem_u32(const void* p) {
    uint32_t a;
    asm("{ .reg .u64 t; cvta.to.shared.u64 t, %1; cvt.u32.u64 %0, t; }" : "=r"(a) : "l"(p));
    return a;
}
__device__ __forceinline__ void cpasync16(void* dst, const void* src) {
    uint32_t d = (uint32_t)__cvta_generic_to_shared(dst);
    asm volatile("cp.async.cg.shared.global [%0], [%1], 16;" :: "r"(d), "l"(src));
}
__device__ __forceinline__ void ldmx4(uint32_t* r, uint32_t addr) {
    asm volatile("ldmatrix.sync.aligned.m8n8.x4.shared.b16 {%0,%1,%2,%3}, [%4];"
                 : "=r"(r[0]), "=r"(r[1]), "=r"(r[2]), "=r"(r[3]) : "r"(addr));
}
__device__ __forceinline__ void ldmx4t(uint32_t* r, uint32_t addr) {
    asm volatile("ldmatrix.sync.aligned.m8n8.x4.trans.shared.b16 {%0,%1,%2,%3}, [%4];"
                 : "=r"(r[0]), "=r"(r[1]), "=r"(r[2]), "=r"(r[3]) : "r"(addr));
}
__device__ __forceinline__ void mma_f16(float* c, const uint32_t* a,
                                        uint32_t b0, uint32_t b1) {
    asm volatile(
        "mma.sync.aligned.m16n8k16.row.col.f32.f16.f16.f32 "
        "{%0,%1,%2,%3}, {%4,%5,%6,%7}, {%8,%9}, {%0,%1,%2,%3};"
        : "+f"(c[0]), "+f"(c[1]), "+f"(c[2]), "+f"(c[3])
        : "r"(a[0]), "r"(a[1]), "r"(a[2]), "r"(a[3]), "r"(b0), "r"(b1));
}
__device__ __forceinline__ uint32_t h2u(float x, float y) {
    __half2 h = __floats2half2_rn(x, y);
    return *(uint32_t*)&h;
}

// ---------------- weight conversion ----------------
__global__ void cvt_half4_kernel(const float* __restrict__ src, __half* __restrict__ dst,
                                 int n4) {
    int i = blockIdx.x * blockDim.x + threadIdx.x;
    if (i >= n4) return;
    float4 v = ((const float4*)src)[i];
    __half2 a = __floats2half2_rn(v.x, v.y);
    __half2 b = __floats2half2_rn(v.z, v.w);
    uint2 u = make_uint2(*(uint32_t*)&a, *(uint32_t*)&b);
    ((uint2*)dst)[i] = u;
}
__global__ void tr_half_kernel(const float* __restrict__ src, __half* __restrict__ dst,
                               int K, int N) {
    __shared__ float t[32][33];
    size_t off = (size_t)blockIdx.z * K * N;
    src += off; dst += off;
    int kb = blockIdx.y * 32, nb = blockIdx.x * 32;
    for (int i = threadIdx.y; i < 32; i += 8)
        t[i][threadIdx.x] = src[(size_t)(kb + i) * N + nb + threadIdx.x];
    __syncthreads();
    for (int i = threadIdx.y; i < 32; i += 8)
        dst[(size_t)(nb + i) * K + kb + threadIdx.x] = __float2half_rn(t[threadIdx.x][i]);
}

// ---------------- patchify -> half: one block (256 thr) per token ----------------
__global__ void patch_kernel(const float* __restrict__ x, __half* __restrict__ xp) {
    int t = blockIdx.x;
    int b = t / NPATCH;
    int p = t - b * NPATCH;
    int gy = p / GRID_, gx = p - gy * GRID_;
    const float* xb = x + ((size_t)b * 3) * IMG * IMG + (gy * PSZ) * IMG + gx * PSZ;
    __half* dst = xp + (size_t)t * DMODEL;
    for (int f = threadIdx.x; f < DMODEL; f += 256) {
        int c  = f >> 8;
        int py = (f >> 4) & 15;
        int px = f & 15;
        dst[f] = __float2half_rn(xb[((size_t)c * IMG + py) * IMG + px]);
    }
}

// ---------------- FP16 mma.sync GEMM (B in [K,N] via ldmatrix.trans) ----------------
// CTA 128x128, 4 warps (2x2 of 64x64), 128 threads, 2 CTAs/SM,
// k-chunk 64, 3-stage ring, prefetch distance 1, single barrier. (R14 frozen config)
// OP 0: +bias -> HALF ; 1: +bias+res -> fp32 ; 2: +bias,GELU -> HALF ; 3: +bias+pos -> fp32
#define KCH  64
#define ASTR 72
#define BSTR 136                                  // 128 + 8 pad halfs
#define A_HALFS (128 * ASTR)                      // 9216
#define B_HALFS (KCH * BSTR)                      // 8704
#define STAGE_HALFS (A_HALFS + B_HALFS)           // 17920
#define STAGE_BYTES (STAGE_HALFS * 2)             // 35840
#define GSTAGES 3
#define GEMM_SMEM (GSTAGES * STAGE_BYTES)         // 107520

template <int OP>
__global__ void __launch_bounds__(128, 2)
gemm_fp16(const __half* __restrict__ A, const __half* __restrict__ B,
          const float* __restrict__ bias, const float* __restrict__ res,
          void* __restrict__ Cout, int M, int N, int K) {
    extern __shared__ __half sm[];
    const int tid = threadIdx.x;
    const int m0 = blockIdx.y * 128, n0 = blockIdx.x * 128;
    const int warp = tid >> 5, lane = tid & 31;
    const int wm = warp >> 1, wn = warp & 1;
    const int g = lane >> 2, tg = lane & 3;

    const uint32_t smb = smem_u32(sm);
    uint32_t aAddr[4], bAddr[4];
#pragma unroll
    for (int mi = 0; mi < 4; mi++)
        aAddr[mi] = smb + ((wm * 64 + mi * 16 + (lane & 15)) * ASTR +
                           ((lane >> 4) & 1) * 8) * 2;
#pragma unroll
    for (int n2 = 0; n2 < 4; n2++)
        bAddr[n2] = smb + A_HALFS * 2 +
                    (((lane & 7) + ((lane >> 3) & 1) * 8) * BSTR +
                     wn * 64 + n2 * 16 + ((lane >> 4) & 1) * 8) * 2;

    float acc[4][8][4];
#pragma unroll
    for (int i = 0; i < 4; i++)
#pragma unroll
        for (int j = 0; j < 8; j++)
#pragma unroll
            for (int c = 0; c < 4; c++) acc[i][j][c] = 0.f;

    const int nIter = K >> 6;

    auto load_stage = [&](int it) {
        __half* As = sm + (it % GSTAGES) * STAGE_HALFS;
        __half* Bs = As + A_HALFS;
        int k0 = it * KCH;
        const __half* Ag = A + (size_t)m0 * K + k0;
        const __half* Bg = B + (size_t)k0 * N + n0;
#pragma unroll
        for (int i = 0; i < 8; i++) {
            int idx = tid + i * 128;
            int r = idx >> 3, c = (idx & 7) * 8;
            cpasync16(&As[r * ASTR + c], Ag + (size_t)r * K + c);
        }
#pragma unroll
        for (int i = 0; i < 8; i++) {
            int idx = tid + i * 128;
            int r = idx >> 4, c = (idx & 15) * 8;
            cpasync16(&Bs[r * BSTR + c], Bg + (size_t)r * N + c);
        }
        asm volatile("cp.async.commit_group;");
    };

    load_stage(0);

    for (int it = 0; it < nIter; it++) {
        if (it + 1 < nIter) {
            load_stage(it + 1);
            asm volatile("cp.async.wait_group 1;");
        } else {
            asm volatile("cp.async.wait_group 0;");
        }
        __syncthreads();

        uint32_t stOff = (uint32_t)((it % GSTAGES) * STAGE_BYTES);
#pragma unroll
        for (int kk = 0; kk < 4; kk++) {
            uint32_t a[4][4], b[4][4];
#pragma unroll
            for (int mi = 0; mi < 4; mi++) ldmx4(a[mi], aAddr[mi] + stOff + kk * 32);
#pragma unroll
            for (int n2 = 0; n2 < 4; n2++)
                ldmx4t(b[n2], bAddr[n2] + stOff + kk * 16 * BSTR * 2);
#pragma unroll
            for (int mi = 0; mi < 4; mi++)
#pragma unroll
                for (int n2 = 0; n2 < 4; n2++) {
                    mma_f16(acc[mi][n2 * 2 + 0], a[mi], b[n2][0], b[n2][1]);
                    mma_f16(acc[mi][n2 * 2 + 1], a[mi], b[n2][2], b[n2][3]);
                }
        }
    }

    // ---- epilogue ----
    float* Cf = (float*)Cout;
    __half* Ch = (__half*)Cout;
#pragma unroll
    for (int mi = 0; mi < 4; mi++) {
        int r0 = m0 + wm * 64 + mi * 16 + g;
#pragma unroll
        for (int ni = 0; ni < 8; ni++) {
            int n = n0 + wn * 64 + ni * 8 + tg * 2;
            float2 bi = *(const float2*)(bias + n);
#pragma unroll
            for (int half = 0; half < 2; half++) {
                int m = r0 + half * 8;
                float v0 = acc[mi][ni][half * 2 + 0] + bi.x;
                float v1 = acc[mi][ni][half * 2 + 1] + bi.y;
                if (OP == 1) {
                    float2 rv = *(const float2*)(res + (size_t)m * N + n);
                    v0 += rv.x; v1 += rv.y;
                }
                if (OP == 3) {
                    float2 rv = *(const float2*)(res + (size_t)(m % NPATCH) * N + n);
                    v0 += rv.x; v1 += rv.y;
                }
                if (OP == 2) {
                    v0 = 0.5f * v0 * (1.0f + erff(v0 * 0.70710678118654752f));
                    v1 = 0.5f * v1 * (1.0f + erff(v1 * 0.70710678118654752f));
                }
                if (OP == 0 || OP == 2) {
                    *(__half2*)(Ch + (size_t)m * N + n) = __floats2half2_rn(v0, v1);
                } else {
                    *(float2*)(Cf + (size_t)m * N + n) = make_float2(v0, v1);
                }
            }
        }
    }
}

// ---------------- attention: tensor-core flash-lite, one CTA per (b,h) ----------------
#define QSTR 72
#define VSTR 216
#define QS_OFF 0
#define KS_OFF (208 * QSTR)
#define VT_OFF (2 * 208 * QSTR)
#define SMEM_ATTN ((VT_OFF + 64 * VSTR) * 2)   // 87552 bytes

__global__ void __launch_bounds__(256, 1)
attn_kernel(const __half* __restrict__ qkv, __half* __restrict__ o) {
    extern __shared__ __half smh[];
    const int tid = threadIdx.x;
    const int bh = blockIdx.x;
    const int b = bh / NHEAD, hh = bh - b * NHEAD;
    const __half* base = qkv + (size_t)b * NPATCH * QKVN + hh * HDIM;

    for (int i = tid; i < 64 * VSTR / 8; i += 256)
        ((uint4*)(smh + VT_OFF))[i] = make_uint4(0u, 0u, 0u, 0u);
    __syncthreads();
    for (int i = tid; i < 208 * 8; i += 256) {
        int r = i >> 3, c = (i & 7) * 8;
        int row = r < NPATCH ? r : NPATCH - 1;
        const __half* src = base + (size_t)row * QKVN;
        *(uint4*)(smh + QS_OFF + r * QSTR + c) = *(const uint4*)(src + c);
        *(uint4*)(smh + KS_OFF + r * QSTR + c) = *(const uint4*)(src + DMODEL + c);
    }
    for (int i = tid; i < NPATCH * 8; i += 256) {
        int kidx = i >> 3, c8 = (i & 7) * 8;
        uint4 v = *(const uint4*)(base + (size_t)kidx * QKVN + 2 * DMODEL + c8);
        const __half* vh = (const __half*)&v;
#pragma unroll
        for (int d = 0; d < 8; d++)
            smh[VT_OFF + (c8 + d) * VSTR + kidx] = vh[d];
    }
    __syncthreads();

    const int warp = tid >> 5, lane = tid & 31;
    const int g = lane >> 2, tg = lane & 3;
    const uint32_t smb = smem_u32(smh);
    const uint32_t qsB = smb + QS_OFF * 2;
    const uint32_t ksB = smb + KS_OFF * 2;
    const uint32_t vtB = smb + VT_OFF * 2;

    const uint32_t aRow = ((lane & 15) * QSTR + ((lane >> 4) & 1) * 8) * 2;
    const uint32_t bRowK = (((lane & 7) + ((lane >> 4) & 1) * 8) * QSTR + ((lane >> 3) & 1) * 8) * 2;
    const uint32_t bRowV = (((lane & 7) + ((lane >> 4) & 1) * 8) * VSTR + ((lane >> 3) & 1) * 8) * 2;

    for (int qc = warp; qc < 13; qc += 8) {
        int q0 = qc * 16;
        uint32_t qa[4][4];
#pragma unroll
        for (int kk = 0; kk < 4; kk++)
            ldmx4(qa[kk], qsB + q0 * QSTR * 2 + aRow + kk * 32);

        float sacc[26][4];
#pragma unroll
        for (int j = 0; j < 26; j++)
#pragma unroll
            for (int c = 0; c < 4; c++) sacc[j][c] = 0.f;

#pragma unroll
        for (int n2 = 0; n2 < 13; n2++) {
#pragma unroll
            for (int kk = 0; kk < 4; kk++) {
                uint32_t bk[4];
                ldmx4(bk, ksB + n2 * 16 * QSTR * 2 + bRowK + kk * 32);
                mma_f16(sacc[n2 * 2 + 0], qa[kk], bk[0], bk[1]);
                mma_f16(sacc[n2 * 2 + 1], qa[kk], bk[2], bk[3]);
            }
        }

        float m0 = -1e30f, m1 = -1e30f;
#pragma unroll
        for (int j = 0; j < 25; j++) {
            bool v = (j < 24) || (tg < 2);
            if (v) {
                m0 = fmaxf(m0, fmaxf(sacc[j][0], sacc[j][1]));
                m1 = fmaxf(m1, fmaxf(sacc[j][2], sacc[j][3]));
            }
        }
        m0 = fmaxf(m0, __shfl_xor_sync(0xffffffffu, m0, 1));
        m0 = fmaxf(m0, __shfl_xor_sync(0xffffffffu, m0, 2));
        m1 = fmaxf(m1, __shfl_xor_sync(0xffffffffu, m1, 1));
        m1 = fmaxf(m1, __shfl_xor_sync(0xffffffffu, m1, 2));

        float l0 = 0.f, l1 = 0.f;
#pragma unroll
        for (int j = 0; j < 26; j++) {
            bool v = (j < 24) || (j == 24 && tg < 2);
            float e0 = v ? __expf(0.125f * (sacc[j][0] - m0)) : 0.f;
            float e1 = v ? __expf(0.125f * (sacc[j][1] - m0)) : 0.f;
            float e2 = v ? __expf(0.125f * (sacc[j][2] - m1)) : 0.f;
            float e3 = v ? __expf(0.125f * (sacc[j][3] - m1)) : 0.f;
            sacc[j][0] = e0; sacc[j][1] = e1; sacc[j][2] = e2; sacc[j][3] = e3;
            l0 += e0 + e1; l1 += e2 + e3;
        }
        l0 += __shfl_xor_sync(0xffffffffu, l0, 1);
        l0 += __shfl_xor_sync(0xffffffffu, l0, 2);
        l1 += __shfl_xor_sync(0xffffffffu, l1, 1);
        l1 += __shfl_xor_sync(0xffffffffu, l1, 2);
        float i0 = 1.f / l0, i1 = 1.f / l1;

        uint32_t pa[13][4];
#pragma unroll
        for (int nt = 0; nt < 13; nt++) {
            pa[nt][0] = h2u(sacc[2 * nt][0] * i0, sacc[2 * nt][1] * i0);
            pa[nt][1] = h2u(sacc[2 * nt][2] * i1, sacc[2 * nt][3] * i1);
            pa[nt][2] = h2u(sacc[2 * nt + 1][0] * i0, sacc[2 * nt + 1][1] * i0);
            pa[nt][3] = h2u(sacc[2 * nt + 1][2] * i1, sacc[2 * nt + 1][3] * i1);
        }

        float oacc[8][4];
#pragma unroll
        for (int j = 0; j < 8; j++)
#pragma unroll
            for (int c = 0; c < 4; c++) oacc[j][c] = 0.f;

#pragma unroll
        for (int dn2 = 0; dn2 < 4; dn2++) {
#pragma unroll
            for (int nt = 0; nt < 13; nt++) {
                uint32_t bv[4];
                ldmx4(bv, vtB + dn2 * 16 * VSTR * 2 + bRowV + nt * 32);
                mma_f16(oacc[dn2 * 2 + 0], pa[nt], bv[0], bv[1]);
                mma_f16(oacc[dn2 * 2 + 1], pa[nt], bv[2], bv[3]);
            }
        }

        int r0 = q0 + g, r1 = q0 + g + 8;
        __half* ob = o + (size_t)b * NPATCH * DMODEL + hh * HDIM;
#pragma unroll
        for (int j8 = 0; j8 < 8; j8++) {
            int col = j8 * 8 + 2 * tg;
            if (r0 < NPATCH)
                *(__half2*)(ob + (size_t)r0 * DMODEL + col) =
                    __floats2half2_rn(oacc[j8][0], oacc[j8][1]);
            if (r1 < NPATCH)
                *(__half2*)(ob + (size_t)r1 * DMODEL + col) =
                    __floats2half2_rn(oacc[j8][2], oacc[j8][3]);
        }
    }
}

// ---------------- layernorm: float4 vectorized, 192 threads/row ----------------
template <int HALF_OUT>
__global__ void ln_kernel(const float* __restrict__ x, const float* __restrict__ w,
                          const float* __restrict__ bb, void* __restrict__ y) {
    int t = blockIdx.x;
    int tid = threadIdx.x;                    // 192
    float4 v = ((const float4*)(x + (size_t)t * DMODEL))[tid];
    float s  = v.x + v.y + v.z + v.w;
    float ss = v.x * v.x + v.y * v.y + v.z * v.z + v.w * v.w;
    __shared__ float redS[6], redQ[6];
#pragma unroll
    for (int off = 16; off; off >>= 1) {
        s  += __shfl_xor_sync(0xffffffffu, s,  off);
        ss += __shfl_xor_sync(0xffffffffu, ss, off);
    }
    if ((tid & 31) == 0) { redS[tid >> 5] = s; redQ[tid >> 5] = ss; }
    __syncthreads();
    if (tid == 0) {
        float a = 0.f, b2 = 0.f;
#pragma unroll
        for (int i = 0; i < 6; i++) { a += redS[i]; b2 += redQ[i]; }
        float mean = a * (1.0f / DMODEL);
        float var = b2 * (1.0f / DMODEL) - mean * mean;
        redS[0] = mean;
        redQ[0] = rsqrtf(var + 1e-5f);
    }
    __syncthreads();
    float mean = redS[0], rstd = redQ[0];
    float4 wv = ((const float4*)w)[tid];
    float4 bv = ((const float4*)bb)[tid];
    float o0 = (v.x - mean) * rstd * wv.x + bv.x;
    float o1 = (v.y - mean) * rstd * wv.y + bv.y;
    float o2 = (v.z - mean) * rstd * wv.z + bv.z;
    float o3 = (v.w - mean) * rstd * wv.w + bv.w;
    if (HALF_OUT) {
        __half2 a = __floats2half2_rn(o0, o1);
        __half2 b = __floats2half2_rn(o2, o3);
        ((uint2*)((__half*)y + (size_t)t * DMODEL))[tid] =
            make_uint2(*(uint32_t*)&a, *(uint32_t*)&b);
    } else {
        ((float4*)((float*)y + (size_t)t * DMODEL))[tid] = make_float4(o0, o1, o2, o3);
    }
}

// ---------------- launch ----------------
extern "C" void kernel_launch(void* const* d_in, const int* in_sizes, int n_in,
                              void* d_out, int out_size) {
    const float* x      = (const float*)d_in[0];
    const float* conv_w = (const float*)d_in[1];
    const float* conv_b = (const float*)d_in[2];
    const float* pos    = (const float*)d_in[3];
    const float* ln1w   = (const float*)d_in[4];
    const float* ln1b   = (const float*)d_in[5];
    const float* qkvw   = (const float*)d_in[6];
    const float* qkvb   = (const float*)d_in[7];
    const float* projw  = (const float*)d_in[8];
    const float* projb  = (const float*)d_in[9];
    const float* ln2w   = (const float*)d_in[10];
    const float* ln2b   = (const float*)d_in[11];
    const float* f1w    = (const float*)d_in[12];
    const float* f1b    = (const float*)d_in[13];
    const float* f2w    = (const float*)d_in[14];
    const float* f2b    = (const float*)d_in[15];
    const float* lnfw   = (const float*)d_in[16];
    const float* lnfb   = (const float*)d_in[17];
    float* out = (float*)d_out;

    float* h;
    __half *qkv, *xp, *y, *o, *act, *wpe, *rqkvw, *rprojw, *rf1w, *rf2w;
    cudaGetSymbolAddress((void**)&h,   g_h);
    cudaGetSymbolAddress((void**)&qkv, h_qkv);
    cudaGetSymbolAddress((void**)&xp,  h_xp);
    cudaGetSymbolAddress((void**)&y,   h_y);
    cudaGetSymbolAddress((void**)&o,   h_o);
    cudaGetSymbolAddress((void**)&act, h_act);
    cudaGetSymbolAddress((void**)&wpe, w_pe);
    cudaGetSymbolAddress((void**)&rqkvw,  w_qkv);
    cudaGetSymbolAddress((void**)&rprojw, w_proj);
    cudaGetSymbolAddress((void**)&rf1w,   w_f1);
    cudaGetSymbolAddress((void**)&rf2w,   w_f2);

    cudaFuncSetAttribute(attn_kernel, cudaFuncAttributeMaxDynamicSharedMemorySize, SMEM_ATTN);
    cudaFuncSetAttribute(gemm_fp16<0>, cudaFuncAttributeMaxDynamicSharedMemorySize, GEMM_SMEM);
    cudaFuncSetAttribute(gemm_fp16<1>, cudaFuncAttributeMaxDynamicSharedMemorySize, GEMM_SMEM);
    cudaFuncSetAttribute(gemm_fp16<2>, cudaFuncAttributeMaxDynamicSharedMemorySize, GEMM_SMEM);
    cudaFuncSetAttribute(gemm_fp16<3>, cudaFuncAttributeMaxDynamicSharedMemorySize, GEMM_SMEM);

    // weights -> half, native [K,N] layout (no transpose); conv_w [N,K] -> [K,N]
    {
        int n4;
        n4 = NLAYER * DMODEL * QKVN   / 4; cvt_half4_kernel<<<(n4 + 255) / 256, 256>>>(qkvw,  rqkvw,  n4);
        n4 = NLAYER * DMODEL * DMODEL / 4; cvt_half4_kernel<<<(n4 + 255) / 256, 256>>>(projw, rprojw, n4);
        n4 = NLAYER * DMODEL * HIDDEN / 4; cvt_half4_kernel<<<(n4 + 255) / 256, 256>>>(f1w,   rf1w,   n4);
        n4 = NLAYER * HIDDEN * DMODEL / 4; cvt_half4_kernel<<<(n4 + 255) / 256, 256>>>(f2w,   rf2w,   n4);
        tr_half_kernel<<<dim3(24, 24, 1), dim3(32, 8)>>>(conv_w, wpe, DMODEL, DMODEL);
    }

    // patchify + patch-embed GEMM (+bias +pos_embed)
    patch_kernel<<<TOK, 256>>>(x, xp);
    gemm_fp16<3><<<dim3(DMODEL / 128, TOK / 128), 128, GEMM_SMEM>>>(
        xp, wpe, conv_b, pos, h, TOK, DMODEL, DMODEL);

    for (int l = 0; l < NLAYER; l++) {
        ln_kernel<1><<<TOK, 192>>>(h, ln1w + (size_t)l * DMODEL, ln1b + (size_t)l * DMODEL, y);
        gemm_fp16<0><<<dim3(QKVN / 128, TOK / 128), 128, GEMM_SMEM>>>(
            y, rqkvw + (size_t)l * DMODEL * QKVN, qkvb + (size_t)l * QKVN, nullptr, qkv,
            TOK, QKVN, DMODEL);
        attn_kernel<<<BATCH * NHEAD, 256, SMEM_ATTN>>>(qkv, o);
        gemm_fp16<1><<<dim3(DMODEL / 128, TOK / 128), 128, GEMM_SMEM>>>(
            o, rprojw + (size_t)l * DMODEL * DMODEL, projb + (size_t)l * DMODEL, h, h,
            TOK, DMODEL, DMODEL);
        ln_kernel<1><<<TOK, 192>>>(h, ln2w + (size_t)l * DMODEL, ln2b + (size_t)l * DMODEL, y);
        gemm_fp16<2><<<dim3(HIDDEN / 128, TOK / 128), 128, GEMM_SMEM>>>(
            y, rf1w + (size_t)l * DMODEL * HIDDEN, f1b + (size_t)l * HIDDEN, nullptr, act,
            TOK, HIDDEN, DMODEL);
        gemm_fp16<1><<<dim3(DMODEL / 128, TOK / 128), 128, GEMM_SMEM>>>(
            act, rf2w + (size_t)l * HIDDEN * DMODEL, f2b + (size_t)l * DMODEL, h, h,
            TOK, DMODEL, HIDDEN);
    }
    ln_kernel<0><<<TOK, 192>>>(h, lnfw, lnfb, out);
}